// round 2
// baseline (speedup 1.0000x reference)
#include <cuda_runtime.h>
#include <math.h>

#define NV   16
#define MAXP 1024
#define DIM  1280
#define NH   16
#define HD   80
#define M_TOT (NV*MAXP)      // 16384
#define QKV_N (3*DIM)        // 3840

// ---- scratch (no allocations allowed) ----
__device__ float g_q[(size_t)NV*NH*MAXP*HD];   // [n][h][p][hd]
__device__ float g_k[(size_t)NV*NH*MAXP*HD];
__device__ float g_v[(size_t)NV*NH*MAXP*HD];
__device__ float g_ao[(size_t)NV*MAXP*DIM];    // attention output, (n,p,d)

// ================= SGEMM: C = A[M,K] @ B[Nc,K]^T + bias =================
#define BM 128
#define BN 128
#define BK 16

// QKV GEMM with scatter epilogue into q/k/v [n][h][p][hd]
__global__ __launch_bounds__(256) void qkv_gemm_kernel(
    const float* __restrict__ X, const float* __restrict__ W,
    const float* __restrict__ bias)
{
    __shared__ float As[BK][BM];
    __shared__ float Bs[BK][BN];
    const int m0 = blockIdx.y * BM;
    const int n0 = blockIdx.x * BN;
    const int tid = threadIdx.x;
    const int tx = tid & 15, ty = tid >> 4;

    float acc[8][8];
#pragma unroll
    for (int i = 0; i < 8; i++)
#pragma unroll
        for (int j = 0; j < 8; j++) acc[i][j] = 0.f;

    for (int k0 = 0; k0 < DIM; k0 += BK) {
#pragma unroll
        for (int i = 0; i < 2; i++) {
            int f = tid * 2 + i;          // 0..511
            int row = f >> 2;
            int seg = f & 3;
            float4 va = *(const float4*)(X + (size_t)(m0 + row) * DIM + k0 + seg * 4);
            As[seg*4+0][row] = va.x; As[seg*4+1][row] = va.y;
            As[seg*4+2][row] = va.z; As[seg*4+3][row] = va.w;
            float4 vb = *(const float4*)(W + (size_t)(n0 + row) * DIM + k0 + seg * 4);
            Bs[seg*4+0][row] = vb.x; Bs[seg*4+1][row] = vb.y;
            Bs[seg*4+2][row] = vb.z; Bs[seg*4+3][row] = vb.w;
        }
        __syncthreads();
#pragma unroll
        for (int kk = 0; kk < BK; kk++) {
            float a[8], b[8];
            *(float4*)&a[0] = *(const float4*)&As[kk][ty*8];
            *(float4*)&a[4] = *(const float4*)&As[kk][ty*8+4];
            *(float4*)&b[0] = *(const float4*)&Bs[kk][tx*8];
            *(float4*)&b[4] = *(const float4*)&Bs[kk][tx*8+4];
#pragma unroll
            for (int i = 0; i < 8; i++)
#pragma unroll
                for (int j = 0; j < 8; j++) acc[i][j] += a[i] * b[j];
        }
        __syncthreads();
    }
    // scatter epilogue
#pragma unroll
    for (int i = 0; i < 8; i++) {
        int m = m0 + ty*8 + i;
        int n = m >> 10;
        int p = m & 1023;
#pragma unroll
        for (int j = 0; j < 8; j++) {
            int jj = n0 + tx*8 + j;
            float val = acc[i][j] + bias[jj];
            int which = jj / DIM;
            int rem = jj - which * DIM;
            int h = rem / HD;
            int dh = rem - h * HD;
            size_t dst = (((size_t)(n*NH + h)) * MAXP + p) * HD + dh;
            if (which == 0)      g_q[dst] = val;
            else if (which == 1) g_k[dst] = val;
            else                 g_v[dst] = val;
        }
    }
}

// Projection GEMM: plain epilogue, A = g_ao
__global__ __launch_bounds__(256) void proj_gemm_kernel(
    const float* __restrict__ W, const float* __restrict__ bias,
    float* __restrict__ out)
{
    __shared__ float As[BK][BM];
    __shared__ float Bs[BK][BN];
    const int m0 = blockIdx.y * BM;
    const int n0 = blockIdx.x * BN;
    const int tid = threadIdx.x;
    const int tx = tid & 15, ty = tid >> 4;
    const float* X = g_ao;

    float acc[8][8];
#pragma unroll
    for (int i = 0; i < 8; i++)
#pragma unroll
        for (int j = 0; j < 8; j++) acc[i][j] = 0.f;

    for (int k0 = 0; k0 < DIM; k0 += BK) {
#pragma unroll
        for (int i = 0; i < 2; i++) {
            int f = tid * 2 + i;
            int row = f >> 2;
            int seg = f & 3;
            float4 va = *(const float4*)(X + (size_t)(m0 + row) * DIM + k0 + seg * 4);
            As[seg*4+0][row] = va.x; As[seg*4+1][row] = va.y;
            As[seg*4+2][row] = va.z; As[seg*4+3][row] = va.w;
            float4 vb = *(const float4*)(W + (size_t)(n0 + row) * DIM + k0 + seg * 4);
            Bs[seg*4+0][row] = vb.x; Bs[seg*4+1][row] = vb.y;
            Bs[seg*4+2][row] = vb.z; Bs[seg*4+3][row] = vb.w;
        }
        __syncthreads();
#pragma unroll
        for (int kk = 0; kk < BK; kk++) {
            float a[8], b[8];
            *(float4*)&a[0] = *(const float4*)&As[kk][ty*8];
            *(float4*)&a[4] = *(const float4*)&As[kk][ty*8+4];
            *(float4*)&b[0] = *(const float4*)&Bs[kk][tx*8];
            *(float4*)&b[4] = *(const float4*)&Bs[kk][tx*8+4];
#pragma unroll
            for (int i = 0; i < 8; i++)
#pragma unroll
                for (int j = 0; j < 8; j++) acc[i][j] += a[i] * b[j];
        }
        __syncthreads();
    }
#pragma unroll
    for (int i = 0; i < 8; i++) {
        int m = m0 + ty*8 + i;
#pragma unroll
        for (int j = 0; j < 8; j++) {
            int jj = n0 + tx*8 + j;
            out[(size_t)m * DIM + jj] = acc[i][j] + bias[jj];
        }
    }
}

// ================= RoPE (in place on g_q, g_k) =================
__global__ __launch_bounds__(256) void rope_kernel(const float* __restrict__ rope)
{
    int idx = blockIdx.x * blockDim.x + threadIdx.x;   // NV*NH*MAXP*40 total
    int j = idx % 40;
    int p = (idx / 40) & 1023;
    int h = (idx / (40 * MAXP)) & 15;
    int n = idx / (40 * MAXP * NH);
    const float c = rope[((size_t)n * MAXP + p) * 160 + j];
    const float s = rope[((size_t)n * MAXP + p) * 160 + 80 + j];
    size_t base = (((size_t)(n * NH + h)) * MAXP + p) * HD;

    float x1 = g_q[base + j], x2 = g_q[base + 40 + j];
    g_q[base + j]      = x1 * c - x2 * s;
    g_q[base + 40 + j] = x2 * c + x1 * s;
    x1 = g_k[base + j]; x2 = g_k[base + 40 + j];
    g_k[base + j]      = x1 * c - x2 * s;
    g_k[base + 40 + j] = x2 * c + x1 * s;
}

// ================= Flash attention =================
// block = 256 threads, one (n, h, 64-query tile)
__global__ __launch_bounds__(256) void attn_kernel(const int* __restrict__ seq_lens)
{
    extern __shared__ float sm[];
    float* Qs   = sm;                 // 64*80
    float* Ks   = Qs + 64 * 80;       // 64*80
    float* Vs   = Ks + 64 * 80;       // 64*80
    float* Ss   = Vs + 64 * 80;       // 64*64
    float* rowm = Ss + 64 * 64;       // 64
    float* rowl = rowm + 64;          // 64
    float* rowc = rowl + 64;          // 64

    const int bid = blockIdx.x;
    const int qt = bid & 15;
    const int h  = (bid >> 4) & 15;
    const int n  = bid >> 8;
    const int L = seq_lens[n];
    const int tid = threadIdx.x;
    const int tx = tid & 15, ty = tid >> 4;
    const float scale = 0.11180339887498948f;  // 1/sqrt(80)

    const float* Qg = g_q + (((size_t)(n * NH + h)) * MAXP + qt * 64) * HD;
    const float* Kg = g_k + (((size_t)(n * NH + h)) * MAXP) * HD;
    const float* Vg = g_v + (((size_t)(n * NH + h)) * MAXP) * HD;

    for (int i = tid; i < 64 * 80; i += 256) Qs[i] = Qg[i];
    if (tid < 64) { rowm[tid] = -1e30f; rowl[tid] = 0.f; }
    __syncthreads();

    float acc[4][5];
#pragma unroll
    for (int i = 0; i < 4; i++)
#pragma unroll
        for (int j = 0; j < 5; j++) acc[i][j] = 0.f;

    for (int k0 = 0; k0 < L; k0 += 64) {
        for (int i = tid; i < 64 * 80; i += 256) {
            Ks[i] = Kg[(size_t)k0 * HD + i];
            Vs[i] = Vg[(size_t)k0 * HD + i];
        }
        __syncthreads();

        // S = (Q @ K^T) * scale, masked
        {
            float s[4][4];
#pragma unroll
            for (int i = 0; i < 4; i++)
#pragma unroll
                for (int j = 0; j < 4; j++) s[i][j] = 0.f;
#pragma unroll 4
            for (int d = 0; d < HD; d++) {
                float a[4], b[4];
#pragma unroll
                for (int i = 0; i < 4; i++) a[i] = Qs[(ty*4 + i) * 80 + d];
#pragma unroll
                for (int j = 0; j < 4; j++) b[j] = Ks[(tx*4 + j) * 80 + d];
#pragma unroll
                for (int i = 0; i < 4; i++)
#pragma unroll
                    for (int j = 0; j < 4; j++) s[i][j] += a[i] * b[j];
            }
#pragma unroll
            for (int i = 0; i < 4; i++)
#pragma unroll
                for (int j = 0; j < 4; j++) {
                    int col = tx*4 + j;
                    float v = s[i][j] * scale;
                    if (k0 + col >= L) v = -1e30f;
                    Ss[(ty*4 + i) * 64 + col] = v;
                }
        }
        __syncthreads();

        // online softmax rows
        if (tid < 64) {
            int r = tid;
            float mold = rowm[r];
            float mx = mold;
            for (int c2 = 0; c2 < 64; c2++) mx = fmaxf(mx, Ss[r*64 + c2]);
            float corr = __expf(mold - mx);
            float l = rowl[r] * corr;
            for (int c2 = 0; c2 < 64; c2++) {
                float e = __expf(Ss[r*64 + c2] - mx);
                Ss[r*64 + c2] = e;
                l += e;
            }
            rowm[r] = mx; rowl[r] = l; rowc[r] = corr;
        }
        __syncthreads();

        // O = O*corr + P @ V
        {
            float f[4];
#pragma unroll
            for (int i = 0; i < 4; i++) f[i] = rowc[ty*4 + i];
#pragma unroll
            for (int i = 0; i < 4; i++)
#pragma unroll
                for (int j = 0; j < 5; j++) acc[i][j] *= f[i];
#pragma unroll 4
            for (int kk = 0; kk < 64; kk++) {
                float a[4], b[5];
#pragma unroll
                for (int i = 0; i < 4; i++) a[i] = Ss[(ty*4 + i) * 64 + kk];
#pragma unroll
                for (int j = 0; j < 5; j++) b[j] = Vs[kk * 80 + tx*5 + j];
#pragma unroll
                for (int i = 0; i < 4; i++)
#pragma unroll
                    for (int j = 0; j < 5; j++) acc[i][j] += a[i] * b[j];
            }
        }
        __syncthreads();
    }

    float invl[4];
#pragma unroll
    for (int i = 0; i < 4; i++) invl[i] = 1.f / rowl[ty*4 + i];
#pragma unroll
    for (int i = 0; i < 4; i++) {
        int q = qt*64 + ty*4 + i;
#pragma unroll
        for (int j = 0; j < 5; j++) {
            int d = h * HD + tx*5 + j;
            g_ao[((size_t)n * MAXP + q) * DIM + d] = acc[i][j] * invl[i];
        }
    }
}

// ================= launch =================
extern "C" void kernel_launch(void* const* d_in, const int* in_sizes, int n_in,
                              void* d_out, int out_size)
{
    const float* hidden  = (const float*)d_in[0];
    const float* rope    = (const float*)d_in[1];
    const int*   seqlens = (const int*)d_in[2];
    const float* w_qkv   = (const float*)d_in[3];
    const float* b_qkv   = (const float*)d_in[4];
    const float* w_proj  = (const float*)d_in[5];
    const float* b_proj  = (const float*)d_in[6];
    float* out = (float*)d_out;

    dim3 gq(QKV_N / BN, M_TOT / BM);          // 30 x 128
    qkv_gemm_kernel<<<gq, 256>>>(hidden, w_qkv, b_qkv);

    int rope_total = NV * NH * MAXP * 40;     // 10,485,760
    rope_kernel<<<rope_total / 256, 256>>>(rope);

    size_t smem = (size_t)(3 * 64 * 80 + 64 * 64 + 3 * 64) * sizeof(float); // 78,592 B
    cudaFuncSetAttribute(attn_kernel, cudaFuncAttributeMaxDynamicSharedMemorySize, (int)smem);
    attn_kernel<<<NV * NH * 16, 256, smem>>>(seqlens);

    dim3 gp(DIM / BN, M_TOT / BM);            // 10 x 128
    proj_gemm_kernel<<<gp, 256>>>(w_proj, b_proj, out);
}

// round 4
// speedup vs baseline: 2.6833x; 2.6833x over previous
#include <cuda_runtime.h>
#include <math.h>
#include <stdint.h>

#define NV   16
#define MAXP 1024
#define DIM  1280
#define NH   16
#define HD   80
#define M_TOT (NV*MAXP)      // 16384
#define QKV_N (3*DIM)        // 3840

// ---- scratch (no allocations allowed) ----
__device__ float g_q[(size_t)NV*NH*MAXP*HD];   // [n][h][p][hd]
__device__ float g_k[(size_t)NV*NH*MAXP*HD];
__device__ float g_v[(size_t)NV*NH*MAXP*HD];
__device__ float g_ao[(size_t)NV*MAXP*DIM];    // attention output, (n,p,d)

// ======================= tf32 helpers =======================
__device__ __forceinline__ uint32_t f2tf32(float f) {
    uint32_t u;
    asm("cvt.rna.tf32.f32 %0, %1;" : "=r"(u) : "f"(f));
    return u;
}

__device__ __forceinline__ void mma_tf32(float c[4], const uint32_t a[4], const uint32_t b[2]) {
    asm volatile(
        "mma.sync.aligned.m16n8k8.row.col.f32.tf32.tf32.f32 "
        "{%0,%1,%2,%3},{%4,%5,%6,%7},{%8,%9},{%0,%1,%2,%3};"
        : "+f"(c[0]), "+f"(c[1]), "+f"(c[2]), "+f"(c[3])
        : "r"(a[0]), "r"(a[1]), "r"(a[2]), "r"(a[3]), "r"(b[0]), "r"(b[1]));
}

// ================= tf32 tensor-core GEMM: C = A[M,K] @ B[Nc,K]^T + bias =================
// BM=128, BN=128, BK=32, 256 threads (8 warps, 2x4), warp tile 64x32.
#define BK 32
#define LDP 36   // smem pitch: (4g+t) mod 32 distinct -> conflict-free frag loads

// EPI: 0 = qkv scatter (A = X arg), 1 = plain to out (A = g_ao device symbol)
template<int EPI>
__global__ __launch_bounds__(256, 2) void gemm_tf32_kernel(
    const float* __restrict__ Xarg, const float* __restrict__ W,
    const float* __restrict__ bias, float* __restrict__ out)
{
    __shared__ uint32_t As[128 * LDP];
    __shared__ uint32_t Bs[128 * LDP];

    // CRITICAL: __device__ symbol must be bound in device code, not passed from host.
    const float* X = (EPI == 1) ? (const float*)g_ao : Xarg;

    const int m0 = blockIdx.y * 128;
    const int n0 = blockIdx.x * 128;
    const int tid = threadIdx.x;
    const int lane = tid & 31;
    const int wid  = tid >> 5;
    const int g = lane >> 2, t = lane & 3;
    const int wm = (wid >> 2) * 64;   // 0 or 64
    const int wn = (wid & 3) * 32;    // 0..96

    float c[4][4][4];
#pragma unroll
    for (int mi = 0; mi < 4; mi++)
#pragma unroll
        for (int ni = 0; ni < 4; ni++)
#pragma unroll
            for (int r = 0; r < 4; r++) c[mi][ni][r] = 0.f;

    for (int k0 = 0; k0 < DIM; k0 += BK) {
        // G2S: 128 rows x 8 float4 each for A and B; convert to tf32 on the way in.
#pragma unroll
        for (int i = 0; i < 4; i++) {
            int task = i * 256 + tid;          // 0..1023
            int row = task >> 3;
            int seg = task & 7;
            float4 va = *(const float4*)(X + (size_t)(m0 + row) * DIM + k0 + seg * 4);
            uint32_t* da = &As[row * LDP + seg * 4];
            da[0] = f2tf32(va.x); da[1] = f2tf32(va.y);
            da[2] = f2tf32(va.z); da[3] = f2tf32(va.w);
            float4 vb = *(const float4*)(W + (size_t)(n0 + row) * DIM + k0 + seg * 4);
            uint32_t* db = &Bs[row * LDP + seg * 4];
            db[0] = f2tf32(vb.x); db[1] = f2tf32(vb.y);
            db[2] = f2tf32(vb.z); db[3] = f2tf32(vb.w);
        }
        __syncthreads();

#pragma unroll
        for (int kk = 0; kk < 4; kk++) {
            uint32_t a[4][4], b[4][2];
#pragma unroll
            for (int mi = 0; mi < 4; mi++) {
                int base = (wm + mi * 16 + g) * LDP + kk * 8 + t;
                a[mi][0] = As[base];
                a[mi][1] = As[base + 8 * LDP];
                a[mi][2] = As[base + 4];
                a[mi][3] = As[base + 8 * LDP + 4];
            }
#pragma unroll
            for (int ni = 0; ni < 4; ni++) {
                int base = (wn + ni * 8 + g) * LDP + kk * 8 + t;
                b[ni][0] = Bs[base];
                b[ni][1] = Bs[base + 4];
            }
#pragma unroll
            for (int mi = 0; mi < 4; mi++)
#pragma unroll
                for (int ni = 0; ni < 4; ni++)
                    mma_tf32(c[mi][ni], a[mi], b[ni]);
        }
        __syncthreads();
    }

    // epilogue
#pragma unroll
    for (int mi = 0; mi < 4; mi++) {
#pragma unroll
        for (int ni = 0; ni < 4; ni++) {
#pragma unroll
            for (int r = 0; r < 4; r++) {
                int row = m0 + wm + mi * 16 + g + ((r >= 2) ? 8 : 0);
                int col = n0 + wn + ni * 8 + 2 * t + (r & 1);
                float val = c[mi][ni][r] + bias[col];
                if (EPI == 1) {
                    out[(size_t)row * DIM + col] = val;
                } else {
                    int n = row >> 10;
                    int p = row & 1023;
                    int which = col / DIM;
                    int rem = col - which * DIM;
                    int h = rem / HD;
                    int dh = rem - h * HD;
                    size_t dst = (((size_t)(n * NH + h)) * MAXP + p) * HD + dh;
                    if (which == 0)      g_q[dst] = val;
                    else if (which == 1) g_k[dst] = val;
                    else                 g_v[dst] = val;
                }
            }
        }
    }
}

// ================= RoPE (in place on g_q, g_k) =================
__global__ __launch_bounds__(256) void rope_kernel(const float* __restrict__ rope)
{
    int idx = blockIdx.x * blockDim.x + threadIdx.x;   // NV*NH*MAXP*40 total
    int j = idx % 40;
    int p = (idx / 40) & 1023;
    int h = (idx / (40 * MAXP)) & 15;
    int n = idx / (40 * MAXP * NH);
    const float c = rope[((size_t)n * MAXP + p) * 160 + j];
    const float s = rope[((size_t)n * MAXP + p) * 160 + 80 + j];
    size_t base = (((size_t)(n * NH + h)) * MAXP + p) * HD;

    float x1 = g_q[base + j], x2 = g_q[base + 40 + j];
    g_q[base + j]      = x1 * c - x2 * s;
    g_q[base + 40 + j] = x2 * c + x1 * s;
    x1 = g_k[base + j]; x2 = g_k[base + 40 + j];
    g_k[base + j]      = x1 * c - x2 * s;
    g_k[base + 40 + j] = x2 * c + x1 * s;
}

// ================= Flash attention (fp32, vectorized smem layout) =================
// block = 256 threads, one (n, h, 64-query tile)
#define SP 68   // S tile pitch
__global__ __launch_bounds__(256) void attn_kernel(const int* __restrict__ seq_lens)
{
    extern __shared__ float sm[];
    float* Qt   = sm;                  // [80][64] d-major, pre-scaled
    float* Kt   = Qt + 80 * 64;        // [80][64] d-major
    float* Vs   = Kt + 80 * 64;        // [64][80] row-major
    float* Ss   = Vs + 64 * 80;        // [64][SP]
    float* red  = Ss + 64 * SP;        // [4][64]
    float* rowm = red + 4 * 64;        // 64
    float* rowl = rowm + 64;           // 64
    float* rowc = rowl + 64;           // 64

    const int bid = blockIdx.x;
    const int qt = bid & 15;
    const int h  = (bid >> 4) & 15;
    const int n  = bid >> 8;
    const int L = seq_lens[n];
    const int tid = threadIdx.x;
    const int tx = tid & 15, ty = tid >> 4;
    const int r64 = tid & 63, q4 = tid >> 6;
    const float scale = 0.11180339887498948f;  // 1/sqrt(80)

    const float* Qg = g_q + (((size_t)(n * NH + h)) * MAXP + qt * 64) * HD;
    const float* Kg = g_k + (((size_t)(n * NH + h)) * MAXP) * HD;
    const float* Vg = g_v + (((size_t)(n * NH + h)) * MAXP) * HD;

    // load Q transposed + pre-scaled
#pragma unroll
    for (int i = 0; i < 5; i++) {
        int tk = i * 256 + tid;        // 1280 tasks
        int r = tk & 63, seg = tk >> 6;
        float4 v = *(const float4*)(Qg + r * HD + seg * 4);
        Qt[(seg * 4 + 0) * 64 + r] = v.x * scale;
        Qt[(seg * 4 + 1) * 64 + r] = v.y * scale;
        Qt[(seg * 4 + 2) * 64 + r] = v.z * scale;
        Qt[(seg * 4 + 3) * 64 + r] = v.w * scale;
    }
    if (tid < 64) { rowm[tid] = -1e30f; rowl[tid] = 0.f; }
    __syncthreads();

    float acc[4][5];
#pragma unroll
    for (int i = 0; i < 4; i++)
#pragma unroll
        for (int j = 0; j < 5; j++) acc[i][j] = 0.f;

    for (int k0 = 0; k0 < L; k0 += 64) {
        // load K transposed, V row-major
#pragma unroll
        for (int i = 0; i < 5; i++) {
            int tk = i * 256 + tid;
            int r = tk & 63, seg = tk >> 6;
            float4 v = *(const float4*)(Kg + (size_t)(k0 + r) * HD + seg * 4);
            Kt[(seg * 4 + 0) * 64 + r] = v.x;
            Kt[(seg * 4 + 1) * 64 + r] = v.y;
            Kt[(seg * 4 + 2) * 64 + r] = v.z;
            Kt[(seg * 4 + 3) * 64 + r] = v.w;
            float4 w = *(const float4*)(Vg + (size_t)(k0 + r) * HD + seg * 4);
            *(float4*)(Vs + r * 80 + seg * 4) = w;
        }
        __syncthreads();

        // S = Q K^T (Q pre-scaled), masked; write row-major [q][k]
        {
            float s[4][4];
#pragma unroll
            for (int i = 0; i < 4; i++)
#pragma unroll
                for (int j = 0; j < 4; j++) s[i][j] = 0.f;
#pragma unroll 8
            for (int d = 0; d < HD; d++) {
                float4 a4 = *(const float4*)(Qt + d * 64 + ty * 4);
                float4 b4 = *(const float4*)(Kt + d * 64 + tx * 4);
                float a[4] = {a4.x, a4.y, a4.z, a4.w};
                float b[4] = {b4.x, b4.y, b4.z, b4.w};
#pragma unroll
                for (int i = 0; i < 4; i++)
#pragma unroll
                    for (int j = 0; j < 4; j++) s[i][j] += a[i] * b[j];
            }
#pragma unroll
            for (int i = 0; i < 4; i++) {
                float4 v;
                v.x = (k0 + tx * 4 + 0 < L) ? s[i][0] : -1e30f;
                v.y = (k0 + tx * 4 + 1 < L) ? s[i][1] : -1e30f;
                v.z = (k0 + tx * 4 + 2 < L) ? s[i][2] : -1e30f;
                v.w = (k0 + tx * 4 + 3 < L) ? s[i][3] : -1e30f;
                *(float4*)(Ss + (ty * 4 + i) * SP + tx * 4) = v;
            }
        }
        __syncthreads();

        // partial max per quarter-row
        {
            float mx = -1e30f;
#pragma unroll
            for (int cc = 0; cc < 16; cc++)
                mx = fmaxf(mx, Ss[r64 * SP + q4 * 16 + cc]);
            red[q4 * 64 + r64] = mx;
        }
        __syncthreads();

        if (tid < 64) {
            float mold = rowm[tid];
            float mx = fmaxf(fmaxf(red[tid], red[64 + tid]),
                             fmaxf(red[128 + tid], red[192 + tid]));
            mx = fmaxf(mx, mold);
            rowc[tid] = __expf(mold - mx);
            rowm[tid] = mx;
        }
        __syncthreads();

        // exp + partial sums
        {
            float mx = rowm[r64];
            float sum = 0.f;
#pragma unroll
            for (int cc = 0; cc < 16; cc++) {
                float e = __expf(Ss[r64 * SP + q4 * 16 + cc] - mx);
                Ss[r64 * SP + q4 * 16 + cc] = e;
                sum += e;
            }
            red[q4 * 64 + r64] = sum;
        }
        __syncthreads();

        if (tid < 64) {
            rowl[tid] = rowl[tid] * rowc[tid] +
                        red[tid] + red[64 + tid] + red[128 + tid] + red[192 + tid];
        }

        // O = O*corr + P @ V
        {
            float f[4];
#pragma unroll
            for (int i = 0; i < 4; i++) f[i] = rowc[ty * 4 + i];
#pragma unroll
            for (int i = 0; i < 4; i++)
#pragma unroll
                for (int j = 0; j < 5; j++) acc[i][j] *= f[i];
#pragma unroll 4
            for (int kk = 0; kk < 64; kk++) {
                float a[4], b[5];
#pragma unroll
                for (int i = 0; i < 4; i++) a[i] = Ss[(ty * 4 + i) * SP + kk];
#pragma unroll
                for (int j = 0; j < 5; j++) b[j] = Vs[kk * 80 + tx * 5 + j];
#pragma unroll
                for (int i = 0; i < 4; i++)
#pragma unroll
                    for (int j = 0; j < 5; j++) acc[i][j] += a[i] * b[j];
            }
        }
        __syncthreads();
    }

    float invl[4];
#pragma unroll
    for (int i = 0; i < 4; i++) invl[i] = 1.f / rowl[ty * 4 + i];
#pragma unroll
    for (int i = 0; i < 4; i++) {
        int q = qt * 64 + ty * 4 + i;
#pragma unroll
        for (int j = 0; j < 5; j++) {
            int d = h * HD + tx * 5 + j;
            g_ao[((size_t)n * MAXP + q) * DIM + d] = acc[i][j] * invl[i];
        }
    }
}

// ================= launch =================
extern "C" void kernel_launch(void* const* d_in, const int* in_sizes, int n_in,
                              void* d_out, int out_size)
{
    const float* hidden  = (const float*)d_in[0];
    const float* rope    = (const float*)d_in[1];
    const int*   seqlens = (const int*)d_in[2];
    const float* w_qkv   = (const float*)d_in[3];
    const float* b_qkv   = (const float*)d_in[4];
    const float* w_proj  = (const float*)d_in[5];
    const float* b_proj  = (const float*)d_in[6];
    float* out = (float*)d_out;

    dim3 gq(QKV_N / 128, M_TOT / 128);        // 30 x 128
    gemm_tf32_kernel<0><<<gq, 256>>>(hidden, w_qkv, b_qkv, nullptr);

    int rope_total = NV * NH * MAXP * 40;     // 10,485,760
    rope_kernel<<<rope_total / 256, 256>>>(rope);

    size_t smem = (size_t)(3 * 80 * 64 + 64 * SP + 4 * 64 + 3 * 64) * sizeof(float);
    cudaFuncSetAttribute(attn_kernel, cudaFuncAttributeMaxDynamicSharedMemorySize, (int)smem);
    attn_kernel<<<NV * NH * 16, 256, smem>>>(seqlens);

    dim3 gp(DIM / 128, M_TOT / 128);          // 10 x 128
    gemm_tf32_kernel<1><<<gp, 256>>>(nullptr, w_proj, b_proj, out);
}

// round 5
// speedup vs baseline: 3.7628x; 1.4023x over previous
#include <cuda_runtime.h>
#include <math.h>
#include <stdint.h>

#define NV   16
#define MAXP 1024
#define DIM  1280
#define NH   16
#define HD   80
#define M_TOT (NV*MAXP)      // 16384
#define QKV_N (3*DIM)        // 3840

// ---- scratch (no allocations allowed) ----
__device__ float g_q[(size_t)NV*NH*MAXP*HD];   // [n][h][p][hd]
__device__ float g_k[(size_t)NV*NH*MAXP*HD];
__device__ float g_v[(size_t)NV*NH*MAXP*HD];
__device__ float g_ao[(size_t)NV*MAXP*DIM];    // attention output, (n,p,d)

// ======================= tf32 helpers =======================
__device__ __forceinline__ uint32_t f2tf32(float f) {
    uint32_t u;
    asm("cvt.rna.tf32.f32 %0, %1;" : "=r"(u) : "f"(f));
    return u;
}

__device__ __forceinline__ void mma_tf32(float c[4], const uint32_t a[4], const uint32_t b[2]) {
    asm volatile(
        "mma.sync.aligned.m16n8k8.row.col.f32.tf32.tf32.f32 "
        "{%0,%1,%2,%3},{%4,%5,%6,%7},{%8,%9},{%0,%1,%2,%3};"
        : "+f"(c[0]), "+f"(c[1]), "+f"(c[2]), "+f"(c[3])
        : "r"(a[0]), "r"(a[1]), "r"(a[2]), "r"(a[3]), "r"(b[0]), "r"(b[1]));
}

// ================= tf32 tensor-core GEMM: C = A[M,K] @ B[Nc,K]^T + bias =================
#define BK 32
#define LDP 36

// EPI: 0 = qkv scatter (A = X arg), 1 = plain to out (A = g_ao device symbol)
template<int EPI>
__global__ __launch_bounds__(256, 2) void gemm_tf32_kernel(
    const float* __restrict__ Xarg, const float* __restrict__ W,
    const float* __restrict__ bias, float* __restrict__ out)
{
    __shared__ uint32_t As[128 * LDP];
    __shared__ uint32_t Bs[128 * LDP];

    const float* X = (EPI == 1) ? (const float*)g_ao : Xarg;

    const int m0 = blockIdx.y * 128;
    const int n0 = blockIdx.x * 128;
    const int tid = threadIdx.x;
    const int lane = tid & 31;
    const int wid  = tid >> 5;
    const int g = lane >> 2, t = lane & 3;
    const int wm = (wid >> 2) * 64;
    const int wn = (wid & 3) * 32;

    float c[4][4][4];
#pragma unroll
    for (int mi = 0; mi < 4; mi++)
#pragma unroll
        for (int ni = 0; ni < 4; ni++)
#pragma unroll
            for (int r = 0; r < 4; r++) c[mi][ni][r] = 0.f;

    for (int k0 = 0; k0 < DIM; k0 += BK) {
#pragma unroll
        for (int i = 0; i < 4; i++) {
            int task = i * 256 + tid;
            int row = task >> 3;
            int seg = task & 7;
            float4 va = *(const float4*)(X + (size_t)(m0 + row) * DIM + k0 + seg * 4);
            uint32_t* da = &As[row * LDP + seg * 4];
            da[0] = f2tf32(va.x); da[1] = f2tf32(va.y);
            da[2] = f2tf32(va.z); da[3] = f2tf32(va.w);
            float4 vb = *(const float4*)(W + (size_t)(n0 + row) * DIM + k0 + seg * 4);
            uint32_t* db = &Bs[row * LDP + seg * 4];
            db[0] = f2tf32(vb.x); db[1] = f2tf32(vb.y);
            db[2] = f2tf32(vb.z); db[3] = f2tf32(vb.w);
        }
        __syncthreads();

#pragma unroll
        for (int kk = 0; kk < 4; kk++) {
            uint32_t a[4][4], b[4][2];
#pragma unroll
            for (int mi = 0; mi < 4; mi++) {
                int base = (wm + mi * 16 + g) * LDP + kk * 8 + t;
                a[mi][0] = As[base];
                a[mi][1] = As[base + 8 * LDP];
                a[mi][2] = As[base + 4];
                a[mi][3] = As[base + 8 * LDP + 4];
            }
#pragma unroll
            for (int ni = 0; ni < 4; ni++) {
                int base = (wn + ni * 8 + g) * LDP + kk * 8 + t;
                b[ni][0] = Bs[base];
                b[ni][1] = Bs[base + 4];
            }
#pragma unroll
            for (int mi = 0; mi < 4; mi++)
#pragma unroll
                for (int ni = 0; ni < 4; ni++)
                    mma_tf32(c[mi][ni], a[mi], b[ni]);
        }
        __syncthreads();
    }

#pragma unroll
    for (int mi = 0; mi < 4; mi++) {
#pragma unroll
        for (int ni = 0; ni < 4; ni++) {
#pragma unroll
            for (int r = 0; r < 4; r++) {
                int row = m0 + wm + mi * 16 + g + ((r >= 2) ? 8 : 0);
                int col = n0 + wn + ni * 8 + 2 * t + (r & 1);
                float val = c[mi][ni][r] + bias[col];
                if (EPI == 1) {
                    out[(size_t)row * DIM + col] = val;
                } else {
                    int n = row >> 10;
                    int p = row & 1023;
                    int which = col / DIM;
                    int rem = col - which * DIM;
                    int h = rem / HD;
                    int dh = rem - h * HD;
                    size_t dst = (((size_t)(n * NH + h)) * MAXP + p) * HD + dh;
                    if (which == 0)      g_q[dst] = val;
                    else if (which == 1) g_k[dst] = val;
                    else                 g_v[dst] = val;
                }
            }
        }
    }
}

// ================= RoPE (in place on g_q, g_k) =================
__global__ __launch_bounds__(256) void rope_kernel(const float* __restrict__ rope)
{
    int idx = blockIdx.x * blockDim.x + threadIdx.x;
    int j = idx % 40;
    int p = (idx / 40) & 1023;
    int h = (idx / (40 * MAXP)) & 15;
    int n = idx / (40 * MAXP * NH);
    const float c = rope[((size_t)n * MAXP + p) * 160 + j];
    const float s = rope[((size_t)n * MAXP + p) * 160 + 80 + j];
    size_t base = (((size_t)(n * NH + h)) * MAXP + p) * HD;

    float x1 = g_q[base + j], x2 = g_q[base + 40 + j];
    g_q[base + j]      = x1 * c - x2 * s;
    g_q[base + 40 + j] = x2 * c + x1 * s;
    x1 = g_k[base + j]; x2 = g_k[base + 40 + j];
    g_k[base + j]      = x1 * c - x2 * s;
    g_k[base + 40 + j] = x2 * c + x1 * s;
}

// ================= Flash attention on tensor cores (tf32 MMA) =================
// block = 256 threads (8 warps as 4x2), one (n, h, 64-query tile)
// Q/K/V in smem pitch 84 (bank-conflict-free fragment loads: 20g+t mod 32 distinct)
#define QP 84
#define SP 68
__global__ __launch_bounds__(256) void attn_kernel(const int* __restrict__ seq_lens)
{
    extern __shared__ float sm[];
    float* Qs   = sm;                  // [64][QP] tf32-rounded, pre-scaled
    float* Ks   = Qs + 64 * QP;        // [64][QP] tf32-rounded
    float* Vs   = Ks + 64 * QP;        // [64][QP] tf32-rounded
    float* Ss   = Vs + 64 * QP;        // [64][SP]
    float* red  = Ss + 64 * SP;        // [4][64]
    float* rowm = red + 4 * 64;        // 64
    float* rowl = rowm + 64;           // 64
    float* rowc = rowl + 64;           // 64

    const int bid = blockIdx.x;
    const int qt = bid & 15;
    const int h  = (bid >> 4) & 15;
    const int n  = bid >> 8;
    const int L = seq_lens[n];
    const int tid = threadIdx.x;
    const int lane = tid & 31;
    const int wid  = tid >> 5;
    const int g = lane >> 2, t = lane & 3;
    const int wq = wid >> 1;           // 0..3 (16 q-rows each)
    const int wc = wid & 1;            // 0..1
    const int r64 = tid & 63, q4 = tid >> 6;
    const float scale = 0.11180339887498948f;  // 1/sqrt(80)

    const float* Qg = g_q + (((size_t)(n * NH + h)) * MAXP + qt * 64) * HD;
    const float* Kg = g_k + (((size_t)(n * NH + h)) * MAXP) * HD;
    const float* Vg = g_v + (((size_t)(n * NH + h)) * MAXP) * HD;

    // load Q: 64x80, cvt to tf32 with scale folded in
#pragma unroll
    for (int i = 0; i < 5; i++) {
        int tk = i * 256 + tid;            // 1280 float4 tasks
        int r = tk & 63, seg = tk >> 6;    // seg 0..19
        float4 v = *(const float4*)(Qg + r * HD + seg * 4);
        float4 o;
        o.x = __uint_as_float(f2tf32(v.x * scale));
        o.y = __uint_as_float(f2tf32(v.y * scale));
        o.z = __uint_as_float(f2tf32(v.z * scale));
        o.w = __uint_as_float(f2tf32(v.w * scale));
        *(float4*)(Qs + r * QP + seg * 4) = o;   // byte offset multiple of 16
    }
    if (tid < 64) { rowm[tid] = -1e30f; rowl[tid] = 0.f; }
    __syncthreads();

    float o[5][4];
#pragma unroll
    for (int ni = 0; ni < 5; ni++)
#pragma unroll
        for (int r = 0; r < 4; r++) o[ni][r] = 0.f;

    for (int k0 = 0; k0 < L; k0 += 64) {
        // load K, V tiles (cvt to tf32)
#pragma unroll
        for (int i = 0; i < 5; i++) {
            int tk = i * 256 + tid;
            int r = tk & 63, seg = tk >> 6;
            float4 v = *(const float4*)(Kg + (size_t)(k0 + r) * HD + seg * 4);
            float4 ok;
            ok.x = __uint_as_float(f2tf32(v.x));
            ok.y = __uint_as_float(f2tf32(v.y));
            ok.z = __uint_as_float(f2tf32(v.z));
            ok.w = __uint_as_float(f2tf32(v.w));
            *(float4*)(Ks + r * QP + seg * 4) = ok;
            float4 w = *(const float4*)(Vg + (size_t)(k0 + r) * HD + seg * 4);
            float4 ov;
            ov.x = __uint_as_float(f2tf32(w.x));
            ov.y = __uint_as_float(f2tf32(w.y));
            ov.z = __uint_as_float(f2tf32(w.z));
            ov.w = __uint_as_float(f2tf32(w.w));
            *(float4*)(Vs + r * QP + seg * 4) = ov;
        }
        __syncthreads();

        // S = Q K^T via MMA; warp computes 16x32: rows wq*16, cols wc*32
        {
            float s[4][4];
#pragma unroll
            for (int ni = 0; ni < 4; ni++)
#pragma unroll
                for (int r = 0; r < 4; r++) s[ni][r] = 0.f;
#pragma unroll
            for (int kk = 0; kk < 10; kk++) {      // K = 80
                uint32_t a[4];
                int base = (wq * 16 + g) * QP + kk * 8 + t;
                a[0] = __float_as_uint(Qs[base]);
                a[1] = __float_as_uint(Qs[base + 8 * QP]);
                a[2] = __float_as_uint(Qs[base + 4]);
                a[3] = __float_as_uint(Qs[base + 8 * QP + 4]);
#pragma unroll
                for (int ni = 0; ni < 4; ni++) {
                    uint32_t b[2];
                    int bb = (wc * 32 + ni * 8 + g) * QP + kk * 8 + t;
                    b[0] = __float_as_uint(Ks[bb]);
                    b[1] = __float_as_uint(Ks[bb + 4]);
                    mma_tf32(s[ni], a, b);
                }
            }
            // store S with key mask (scale already in Q)
#pragma unroll
            for (int ni = 0; ni < 4; ni++) {
                int col = wc * 32 + ni * 8 + 2 * t;
                int r0 = wq * 16 + g, r1 = r0 + 8;
                Ss[r0 * SP + col]     = (k0 + col     < L) ? s[ni][0] : -1e30f;
                Ss[r0 * SP + col + 1] = (k0 + col + 1 < L) ? s[ni][1] : -1e30f;
                Ss[r1 * SP + col]     = (k0 + col     < L) ? s[ni][2] : -1e30f;
                Ss[r1 * SP + col + 1] = (k0 + col + 1 < L) ? s[ni][3] : -1e30f;
            }
        }
        __syncthreads();

        // partial max per quarter-row
        {
            float mx = -1e30f;
#pragma unroll
            for (int cc = 0; cc < 16; cc++)
                mx = fmaxf(mx, Ss[r64 * SP + q4 * 16 + cc]);
            red[q4 * 64 + r64] = mx;
        }
        __syncthreads();

        if (tid < 64) {
            float mold = rowm[tid];
            float mx = fmaxf(fmaxf(red[tid], red[64 + tid]),
                             fmaxf(red[128 + tid], red[192 + tid]));
            mx = fmaxf(mx, mold);
            rowc[tid] = __expf(mold - mx);
            rowm[tid] = mx;
        }
        __syncthreads();

        // exp + partial sums
        {
            float mx = rowm[r64];
            float sum = 0.f;
#pragma unroll
            for (int cc = 0; cc < 16; cc++) {
                float e = __expf(Ss[r64 * SP + q4 * 16 + cc] - mx);
                Ss[r64 * SP + q4 * 16 + cc] = e;
                sum += e;
            }
            red[q4 * 64 + r64] = sum;
        }
        __syncthreads();

        if (tid < 64) {
            rowl[tid] = rowl[tid] * rowc[tid] +
                        red[tid] + red[64 + tid] + red[128 + tid] + red[192 + tid];
        }
        __syncthreads();

        // O = O*corr + P @ V via MMA; warp computes 16x40: rows wq*16, cols wc*40
        {
            float f0 = rowc[wq * 16 + g];
            float f1 = rowc[wq * 16 + g + 8];
#pragma unroll
            for (int ni = 0; ni < 5; ni++) {
                o[ni][0] *= f0; o[ni][1] *= f0;
                o[ni][2] *= f1; o[ni][3] *= f1;
            }
#pragma unroll
            for (int kk = 0; kk < 8; kk++) {       // K = 64 keys
                uint32_t a[4];
                int base = (wq * 16 + g) * SP + kk * 8 + t;
                a[0] = f2tf32(Ss[base]);
                a[1] = f2tf32(Ss[base + 8 * SP]);
                a[2] = f2tf32(Ss[base + 4]);
                a[3] = f2tf32(Ss[base + 8 * SP + 4]);
#pragma unroll
                for (int ni = 0; ni < 5; ni++) {
                    uint32_t b[2];
                    int bb = (kk * 8 + t) * QP + wc * 40 + ni * 8 + g;
                    b[0] = __float_as_uint(Vs[bb]);
                    b[1] = __float_as_uint(Vs[bb + 4 * QP]);
                    mma_tf32(o[ni], a, b);
                }
            }
        }
        __syncthreads();
    }

    // epilogue: divide by l, store to g_ao
    {
        float il0 = 1.f / rowl[wq * 16 + g];
        float il1 = 1.f / rowl[wq * 16 + g + 8];
        int q0 = qt * 64 + wq * 16 + g;
        int q1 = q0 + 8;
#pragma unroll
        for (int ni = 0; ni < 5; ni++) {
            int d = h * HD + wc * 40 + ni * 8 + 2 * t;
            g_ao[((size_t)n * MAXP + q0) * DIM + d]     = o[ni][0] * il0;
            g_ao[((size_t)n * MAXP + q0) * DIM + d + 1] = o[ni][1] * il0;
            g_ao[((size_t)n * MAXP + q1) * DIM + d]     = o[ni][2] * il1;
            g_ao[((size_t)n * MAXP + q1) * DIM + d + 1] = o[ni][3] * il1;
        }
    }
}

// ================= launch =================
extern "C" void kernel_launch(void* const* d_in, const int* in_sizes, int n_in,
                              void* d_out, int out_size)
{
    const float* hidden  = (const float*)d_in[0];
    const float* rope    = (const float*)d_in[1];
    const int*   seqlens = (const int*)d_in[2];
    const float* w_qkv   = (const float*)d_in[3];
    const float* b_qkv   = (const float*)d_in[4];
    const float* w_proj  = (const float*)d_in[5];
    const float* b_proj  = (const float*)d_in[6];
    float* out = (float*)d_out;

    dim3 gq(QKV_N / 128, M_TOT / 128);
    gemm_tf32_kernel<0><<<gq, 256>>>(hidden, w_qkv, b_qkv, nullptr);

    int rope_total = NV * NH * MAXP * 40;
    rope_kernel<<<rope_total / 256, 256>>>(rope);

    size_t smem = (size_t)(3 * 64 * QP + 64 * SP + 4 * 64 + 3 * 64) * sizeof(float); // 83,712 B
    cudaFuncSetAttribute(attn_kernel, cudaFuncAttributeMaxDynamicSharedMemorySize, (int)smem);
    attn_kernel<<<NV * NH * 16, 256, smem>>>(seqlens);

    dim3 gp(DIM / 128, M_TOT / 128);
    gemm_tf32_kernel<1><<<gp, 256>>>(nullptr, w_proj, b_proj, out);
}

// round 6
// speedup vs baseline: 3.8514x; 1.0236x over previous
#include <cuda_runtime.h>
#include <math.h>
#include <stdint.h>

#define NV   16
#define MAXP 1024
#define DIM  1280
#define NH   16
#define HD   80
#define M_TOT (NV*MAXP)      // 16384
#define QKV_N (3*DIM)        // 3840

// ---- scratch (no allocations allowed) ----
__device__ float g_q[(size_t)NV*NH*MAXP*HD];   // [n][h][p][hd]
__device__ float g_k[(size_t)NV*NH*MAXP*HD];
__device__ float g_v[(size_t)NV*NH*MAXP*HD];
__device__ float g_ao[(size_t)NV*MAXP*DIM];    // attention output, (n,p,d)

// ======================= tf32 helpers =======================
__device__ __forceinline__ uint32_t f2tf32(float f) {
    uint32_t u;
    asm("cvt.rna.tf32.f32 %0, %1;" : "=r"(u) : "f"(f));
    return u;
}

__device__ __forceinline__ void mma_tf32(float c[4], const uint32_t a[4], const uint32_t b[2]) {
    asm volatile(
        "mma.sync.aligned.m16n8k8.row.col.f32.tf32.tf32.f32 "
        "{%0,%1,%2,%3},{%4,%5,%6,%7},{%8,%9},{%0,%1,%2,%3};"
        : "+f"(c[0]), "+f"(c[1]), "+f"(c[2]), "+f"(c[3])
        : "r"(a[0]), "r"(a[1]), "r"(a[2]), "r"(a[3]), "r"(b[0]), "r"(b[1]));
}

// ================= tf32 tensor-core GEMM: C = A[M,K] @ B[Nc,K]^T + bias =================
// BM=128, BN=128, BK=32, 256 threads (8 warps, 2x4), warp tile 64x32.
// Double-buffered smem + register staging: LDG(kt+1) || MMA(kt) || cvt+STS(kt+1).
#define BK 32
#define LDP 36
#define BUFSZ (128 * LDP)
#define NKT (DIM / BK)   // 40

// EPI: 0 = qkv scatter (A = X arg), 1 = plain to out (A = g_ao device symbol)
template<int EPI>
__global__ __launch_bounds__(256, 2) void gemm_tf32_kernel(
    const float* __restrict__ Xarg, const float* __restrict__ W,
    const float* __restrict__ bias, float* __restrict__ out)
{
    extern __shared__ uint32_t smem_u[];
    uint32_t* As = smem_u;             // [2][BUFSZ]
    uint32_t* Bs = smem_u + 2 * BUFSZ; // [2][BUFSZ]

    const float* X = (EPI == 1) ? (const float*)g_ao : Xarg;

    const int m0 = blockIdx.y * 128;
    const int n0 = blockIdx.x * 128;
    const int tid = threadIdx.x;
    const int lane = tid & 31;
    const int wid  = tid >> 5;
    const int g = lane >> 2, t = lane & 3;
    const int wm = (wid >> 2) * 64;
    const int wn = (wid & 3) * 32;

    // per-thread load/store offsets (4 tasks: one A float4 + one B float4 each)
    size_t goffA[4], goffB[4];
    int soff[4];
#pragma unroll
    for (int i = 0; i < 4; i++) {
        int task = i * 256 + tid;      // 0..1023
        int row = task >> 3;
        int seg = task & 7;
        goffA[i] = (size_t)(m0 + row) * DIM + seg * 4;
        goffB[i] = (size_t)(n0 + row) * DIM + seg * 4;
        soff[i]  = row * LDP + seg * 4;
    }

    float c[4][4][4];
#pragma unroll
    for (int mi = 0; mi < 4; mi++)
#pragma unroll
        for (int ni = 0; ni < 4; ni++)
#pragma unroll
            for (int r = 0; r < 4; r++) c[mi][ni][r] = 0.f;

    float4 ra[4], rb[4];

    // prologue: load tile 0, store to buf 0
#pragma unroll
    for (int i = 0; i < 4; i++) {
        ra[i] = *(const float4*)(X + goffA[i]);
        rb[i] = *(const float4*)(W + goffB[i]);
    }
#pragma unroll
    for (int i = 0; i < 4; i++) {
        uint32_t* da = &As[soff[i]];
        da[0] = f2tf32(ra[i].x); da[1] = f2tf32(ra[i].y);
        da[2] = f2tf32(ra[i].z); da[3] = f2tf32(ra[i].w);
        uint32_t* db = &Bs[soff[i]];
        db[0] = f2tf32(rb[i].x); db[1] = f2tf32(rb[i].y);
        db[2] = f2tf32(rb[i].z); db[3] = f2tf32(rb[i].w);
    }
    __syncthreads();

    for (int kt = 0; kt < NKT; kt++) {
        const int cur = kt & 1;
        const int nxt = cur ^ 1;

        // issue global loads for next tile (latency hidden by MMAs below)
        if (kt + 1 < NKT) {
            size_t k1 = (size_t)(kt + 1) * BK;
#pragma unroll
            for (int i = 0; i < 4; i++) {
                ra[i] = *(const float4*)(X + goffA[i] + k1);
                rb[i] = *(const float4*)(W + goffB[i] + k1);
            }
        }

        // compute on current buffer
        const uint32_t* Ab = As + cur * BUFSZ;
        const uint32_t* Bb = Bs + cur * BUFSZ;
#pragma unroll
        for (int kk = 0; kk < 4; kk++) {
            uint32_t a[4][4], b[4][2];
#pragma unroll
            for (int mi = 0; mi < 4; mi++) {
                int base = (wm + mi * 16 + g) * LDP + kk * 8 + t;
                a[mi][0] = Ab[base];
                a[mi][1] = Ab[base + 8 * LDP];
                a[mi][2] = Ab[base + 4];
                a[mi][3] = Ab[base + 8 * LDP + 4];
            }
#pragma unroll
            for (int ni = 0; ni < 4; ni++) {
                int base = (wn + ni * 8 + g) * LDP + kk * 8 + t;
                b[ni][0] = Bb[base];
                b[ni][1] = Bb[base + 4];
            }
#pragma unroll
            for (int mi = 0; mi < 4; mi++)
#pragma unroll
                for (int ni = 0; ni < 4; ni++)
                    mma_tf32(c[mi][ni], a[mi], b[ni]);
        }

        // convert + store next tile into other buffer
        if (kt + 1 < NKT) {
            uint32_t* An = As + nxt * BUFSZ;
            uint32_t* Bn = Bs + nxt * BUFSZ;
#pragma unroll
            for (int i = 0; i < 4; i++) {
                uint32_t* da = &An[soff[i]];
                da[0] = f2tf32(ra[i].x); da[1] = f2tf32(ra[i].y);
                da[2] = f2tf32(ra[i].z); da[3] = f2tf32(ra[i].w);
                uint32_t* db = &Bn[soff[i]];
                db[0] = f2tf32(rb[i].x); db[1] = f2tf32(rb[i].y);
                db[2] = f2tf32(rb[i].z); db[3] = f2tf32(rb[i].w);
            }
        }
        __syncthreads();
    }

    // epilogue
#pragma unroll
    for (int mi = 0; mi < 4; mi++) {
#pragma unroll
        for (int ni = 0; ni < 4; ni++) {
#pragma unroll
            for (int r = 0; r < 4; r++) {
                int row = m0 + wm + mi * 16 + g + ((r >= 2) ? 8 : 0);
                int col = n0 + wn + ni * 8 + 2 * t + (r & 1);
                float val = c[mi][ni][r] + bias[col];
                if (EPI == 1) {
                    out[(size_t)row * DIM + col] = val;
                } else {
                    int n = row >> 10;
                    int p = row & 1023;
                    int which = col / DIM;
                    int rem = col - which * DIM;
                    int h = rem / HD;
                    int dh = rem - h * HD;
                    size_t dst = (((size_t)(n * NH + h)) * MAXP + p) * HD + dh;
                    if (which == 0)      g_q[dst] = val;
                    else if (which == 1) g_k[dst] = val;
                    else                 g_v[dst] = val;
                }
            }
        }
    }
}

// ================= RoPE (in place on g_q, g_k) =================
__global__ __launch_bounds__(256) void rope_kernel(const float* __restrict__ rope)
{
    int idx = blockIdx.x * blockDim.x + threadIdx.x;
    int j = idx % 40;
    int p = (idx / 40) & 1023;
    int h = (idx / (40 * MAXP)) & 15;
    int n = idx / (40 * MAXP * NH);
    const float c = rope[((size_t)n * MAXP + p) * 160 + j];
    const float s = rope[((size_t)n * MAXP + p) * 160 + 80 + j];
    size_t base = (((size_t)(n * NH + h)) * MAXP + p) * HD;

    float x1 = g_q[base + j], x2 = g_q[base + 40 + j];
    g_q[base + j]      = x1 * c - x2 * s;
    g_q[base + 40 + j] = x2 * c + x1 * s;
    x1 = g_k[base + j]; x2 = g_k[base + 40 + j];
    g_k[base + j]      = x1 * c - x2 * s;
    g_k[base + 40 + j] = x2 * c + x1 * s;
}

// ================= Flash attention on tensor cores (tf32 MMA) =================
// block = 256 threads (8 warps as 4x2), one (n, h, 64-query tile)
#define QP 84
#define SP 68
__global__ __launch_bounds__(256) void attn_kernel(const int* __restrict__ seq_lens)
{
    extern __shared__ float sm[];
    float* Qs   = sm;                  // [64][QP] tf32-rounded, pre-scaled
    float* Ks   = Qs + 64 * QP;        // [64][QP] tf32-rounded
    float* Vs   = Ks + 64 * QP;        // [64][QP] tf32-rounded
    float* Ss   = Vs + 64 * QP;        // [64][SP]
    float* red  = Ss + 64 * SP;        // [4][64]
    float* rowm = red + 4 * 64;        // 64
    float* rowl = rowm + 64;           // 64
    float* rowc = rowl + 64;           // 64

    const int bid = blockIdx.x;
    const int qt = bid & 15;
    const int h  = (bid >> 4) & 15;
    const int n  = bid >> 8;
    const int L = seq_lens[n];
    const int tid = threadIdx.x;
    const int lane = tid & 31;
    const int wid  = tid >> 5;
    const int g = lane >> 2, t = lane & 3;
    const int wq = wid >> 1;
    const int wc = wid & 1;
    const int r64 = tid & 63, q4 = tid >> 6;
    const float scale = 0.11180339887498948f;  // 1/sqrt(80)

    const float* Qg = g_q + (((size_t)(n * NH + h)) * MAXP + qt * 64) * HD;
    const float* Kg = g_k + (((size_t)(n * NH + h)) * MAXP) * HD;
    const float* Vg = g_v + (((size_t)(n * NH + h)) * MAXP) * HD;

#pragma unroll
    for (int i = 0; i < 5; i++) {
        int tk = i * 256 + tid;
        int r = tk & 63, seg = tk >> 6;
        float4 v = *(const float4*)(Qg + r * HD + seg * 4);
        float4 o;
        o.x = __uint_as_float(f2tf32(v.x * scale));
        o.y = __uint_as_float(f2tf32(v.y * scale));
        o.z = __uint_as_float(f2tf32(v.z * scale));
        o.w = __uint_as_float(f2tf32(v.w * scale));
        *(float4*)(Qs + r * QP + seg * 4) = o;
    }
    if (tid < 64) { rowm[tid] = -1e30f; rowl[tid] = 0.f; }
    __syncthreads();

    float o[5][4];
#pragma unroll
    for (int ni = 0; ni < 5; ni++)
#pragma unroll
        for (int r = 0; r < 4; r++) o[ni][r] = 0.f;

    for (int k0 = 0; k0 < L; k0 += 64) {
#pragma unroll
        for (int i = 0; i < 5; i++) {
            int tk = i * 256 + tid;
            int r = tk & 63, seg = tk >> 6;
            float4 v = *(const float4*)(Kg + (size_t)(k0 + r) * HD + seg * 4);
            float4 ok;
            ok.x = __uint_as_float(f2tf32(v.x));
            ok.y = __uint_as_float(f2tf32(v.y));
            ok.z = __uint_as_float(f2tf32(v.z));
            ok.w = __uint_as_float(f2tf32(v.w));
            *(float4*)(Ks + r * QP + seg * 4) = ok;
            float4 w = *(const float4*)(Vg + (size_t)(k0 + r) * HD + seg * 4);
            float4 ov;
            ov.x = __uint_as_float(f2tf32(w.x));
            ov.y = __uint_as_float(f2tf32(w.y));
            ov.z = __uint_as_float(f2tf32(w.z));
            ov.w = __uint_as_float(f2tf32(w.w));
            *(float4*)(Vs + r * QP + seg * 4) = ov;
        }
        __syncthreads();

        // S = Q K^T via MMA; warp computes 16x32
        {
            float s[4][4];
#pragma unroll
            for (int ni = 0; ni < 4; ni++)
#pragma unroll
                for (int r = 0; r < 4; r++) s[ni][r] = 0.f;
#pragma unroll
            for (int kk = 0; kk < 10; kk++) {
                uint32_t a[4];
                int base = (wq * 16 + g) * QP + kk * 8 + t;
                a[0] = __float_as_uint(Qs[base]);
                a[1] = __float_as_uint(Qs[base + 8 * QP]);
                a[2] = __float_as_uint(Qs[base + 4]);
                a[3] = __float_as_uint(Qs[base + 8 * QP + 4]);
#pragma unroll
                for (int ni = 0; ni < 4; ni++) {
                    uint32_t b[2];
                    int bb = (wc * 32 + ni * 8 + g) * QP + kk * 8 + t;
                    b[0] = __float_as_uint(Ks[bb]);
                    b[1] = __float_as_uint(Ks[bb + 4]);
                    mma_tf32(s[ni], a, b);
                }
            }
#pragma unroll
            for (int ni = 0; ni < 4; ni++) {
                int col = wc * 32 + ni * 8 + 2 * t;
                int r0 = wq * 16 + g, r1 = r0 + 8;
                Ss[r0 * SP + col]     = (k0 + col     < L) ? s[ni][0] : -1e30f;
                Ss[r0 * SP + col + 1] = (k0 + col + 1 < L) ? s[ni][1] : -1e30f;
                Ss[r1 * SP + col]     = (k0 + col     < L) ? s[ni][2] : -1e30f;
                Ss[r1 * SP + col + 1] = (k0 + col + 1 < L) ? s[ni][3] : -1e30f;
            }
        }
        __syncthreads();

        {
            float mx = -1e30f;
#pragma unroll
            for (int cc = 0; cc < 16; cc++)
                mx = fmaxf(mx, Ss[r64 * SP + q4 * 16 + cc]);
            red[q4 * 64 + r64] = mx;
        }
        __syncthreads();

        if (tid < 64) {
            float mold = rowm[tid];
            float mx = fmaxf(fmaxf(red[tid], red[64 + tid]),
                             fmaxf(red[128 + tid], red[192 + tid]));
            mx = fmaxf(mx, mold);
            rowc[tid] = __expf(mold - mx);
            rowm[tid] = mx;
        }
        __syncthreads();

        {
            float mx = rowm[r64];
            float sum = 0.f;
#pragma unroll
            for (int cc = 0; cc < 16; cc++) {
                float e = __expf(Ss[r64 * SP + q4 * 16 + cc] - mx);
                Ss[r64 * SP + q4 * 16 + cc] = e;
                sum += e;
            }
            red[q4 * 64 + r64] = sum;
        }
        __syncthreads();

        if (tid < 64) {
            rowl[tid] = rowl[tid] * rowc[tid] +
                        red[tid] + red[64 + tid] + red[128 + tid] + red[192 + tid];
        }
        __syncthreads();

        // O = O*corr + P @ V via MMA
        {
            float f0 = rowc[wq * 16 + g];
            float f1 = rowc[wq * 16 + g + 8];
#pragma unroll
            for (int ni = 0; ni < 5; ni++) {
                o[ni][0] *= f0; o[ni][1] *= f0;
                o[ni][2] *= f1; o[ni][3] *= f1;
            }
#pragma unroll
            for (int kk = 0; kk < 8; kk++) {
                uint32_t a[4];
                int base = (wq * 16 + g) * SP + kk * 8 + t;
                a[0] = f2tf32(Ss[base]);
                a[1] = f2tf32(Ss[base + 8 * SP]);
                a[2] = f2tf32(Ss[base + 4]);
                a[3] = f2tf32(Ss[base + 8 * SP + 4]);
#pragma unroll
                for (int ni = 0; ni < 5; ni++) {
                    uint32_t b[2];
                    int bb = (kk * 8 + t) * QP + wc * 40 + ni * 8 + g;
                    b[0] = __float_as_uint(Vs[bb]);
                    b[1] = __float_as_uint(Vs[bb + 4 * QP]);
                    mma_tf32(o[ni], a, b);
                }
            }
        }
        __syncthreads();
    }

    {
        float il0 = 1.f / rowl[wq * 16 + g];
        float il1 = 1.f / rowl[wq * 16 + g + 8];
        int q0 = qt * 64 + wq * 16 + g;
        int q1 = q0 + 8;
#pragma unroll
        for (int ni = 0; ni < 5; ni++) {
            int d = h * HD + wc * 40 + ni * 8 + 2 * t;
            g_ao[((size_t)n * MAXP + q0) * DIM + d]     = o[ni][0] * il0;
            g_ao[((size_t)n * MAXP + q0) * DIM + d + 1] = o[ni][1] * il0;
            g_ao[((size_t)n * MAXP + q1) * DIM + d]     = o[ni][2] * il1;
            g_ao[((size_t)n * MAXP + q1) * DIM + d + 1] = o[ni][3] * il1;
        }
    }
}

// ================= launch =================
extern "C" void kernel_launch(void* const* d_in, const int* in_sizes, int n_in,
                              void* d_out, int out_size)
{
    const float* hidden  = (const float*)d_in[0];
    const float* rope    = (const float*)d_in[1];
    const int*   seqlens = (const int*)d_in[2];
    const float* w_qkv   = (const float*)d_in[3];
    const float* b_qkv   = (const float*)d_in[4];
    const float* w_proj  = (const float*)d_in[5];
    const float* b_proj  = (const float*)d_in[6];
    float* out = (float*)d_out;

    size_t gsmem = (size_t)4 * BUFSZ * sizeof(uint32_t);   // 73,728 B
    cudaFuncSetAttribute(gemm_tf32_kernel<0>, cudaFuncAttributeMaxDynamicSharedMemorySize, (int)gsmem);
    cudaFuncSetAttribute(gemm_tf32_kernel<1>, cudaFuncAttributeMaxDynamicSharedMemorySize, (int)gsmem);

    dim3 gq(QKV_N / 128, M_TOT / 128);
    gemm_tf32_kernel<0><<<gq, 256, gsmem>>>(hidden, w_qkv, b_qkv, nullptr);

    int rope_total = NV * NH * MAXP * 40;
    rope_kernel<<<rope_total / 256, 256>>>(rope);

    size_t smem = (size_t)(3 * 64 * QP + 64 * SP + 4 * 64 + 3 * 64) * sizeof(float);
    cudaFuncSetAttribute(attn_kernel, cudaFuncAttributeMaxDynamicSharedMemorySize, (int)smem);
    attn_kernel<<<NV * NH * 16, 256, smem>>>(seqlens);

    dim3 gp(DIM / 128, M_TOT / 128);
    gemm_tf32_kernel<1><<<gp, 256, gsmem>>>(nullptr, w_proj, b_proj, out);
}